// round 17
// baseline (speedup 1.0000x reference)
#include <cuda_runtime.h>
#include <cuda_bf16.h>
#include <cstdint>

#define T_DIM 512
#define B_DIM 128
#define E_DIM 256
#define U_DIM 256

// Scratch for xW[t][b][u]  (64 MB fp32 — L2-resident)
__device__ float g_xw[T_DIM * B_DIM * U_DIM];

// ---------------- helpers ----------------
__device__ __forceinline__ uint32_t smem_u32(const void* p) {
    uint32_t a;
    asm("{ .reg .u64 t; cvta.to.shared.u64 t, %1; cvt.u32.u64 %0, t; }" : "=r"(a) : "l"(p));
    return a;
}
__device__ __forceinline__ uint32_t packbf(float a, float b) {
    __nv_bfloat162 t = __floats2bfloat162_rn(a, b);
    return *reinterpret_cast<uint32_t*>(&t);
}
__device__ __forceinline__ void ldsm_x4(uint32_t* r, uint32_t addr) {
    asm volatile("ldmatrix.sync.aligned.m8n8.x4.shared.b16 {%0,%1,%2,%3}, [%4];"
                 : "=r"(r[0]), "=r"(r[1]), "=r"(r[2]), "=r"(r[3]) : "r"(addr));
}
__device__ __forceinline__ void ldsm_x2(uint32_t* r, uint32_t addr) {
    asm volatile("ldmatrix.sync.aligned.m8n8.x2.shared.b16 {%0,%1}, [%2];"
                 : "=r"(r[0]), "=r"(r[1]) : "r"(addr));
}
__device__ __forceinline__ void mma_bf16(float* c, const uint32_t* a, const uint32_t* b) {
    asm volatile("mma.sync.aligned.m16n8k16.row.col.f32.bf16.bf16.f32 "
                 "{%0,%1,%2,%3}, {%4,%5,%6,%7}, {%8,%9}, {%0,%1,%2,%3};"
                 : "+f"(c[0]), "+f"(c[1]), "+f"(c[2]), "+f"(c[3])
                 : "r"(a[0]), "r"(a[1]), "r"(a[2]), "r"(a[3]), "r"(b[0]), "r"(b[1]));
}
__device__ __forceinline__ void cpasync16(uint32_t dst, const void* src) {
    asm volatile("cp.async.ca.shared.global [%0], [%1], 16;" :: "r"(dst), "l"(src) : "memory");
}

// ---------------- Kernel 1: xW[t][b][u] = emb[token(b,t)] . W[u] ----------------
static constexpr int APAD = 264;
static constexpr int AS_OFF = 0;
static constexpr int BS_OFF = 128 * APAD * 2;
static constexpr int XW_SMEM = BS_OFF + 256 * APAD * 2;

__global__ void __launch_bounds__(256, 1)
xw_kernel(const int* __restrict__ sentence, const float* __restrict__ emb,
          const float* __restrict__ W) {
    extern __shared__ char smem[];
    const int tid = threadIdx.x, t = blockIdx.x;
    const int wid = tid >> 5, lane = tid & 31;
    const uint32_t sb = smem_u32(smem);

    {
        const int sub = tid & 7;
        #pragma unroll
        for (int p = 0; p < 4; p++) {
            const int r = p * 32 + (tid >> 3);
            const int tok = sentence[r * T_DIM + t];
            const float4* src = reinterpret_cast<const float4*>(emb + (size_t)tok * E_DIM) + sub;
            char* dstrow = smem + AS_OFF + r * (APAD * 2);
            #pragma unroll
            for (int j = 0; j < 8; j++) {
                float4 v = src[j * 8];
                *reinterpret_cast<uint2*>(dstrow + (sub + j * 8) * 8) =
                    make_uint2(packbf(v.x, v.y), packbf(v.z, v.w));
            }
        }
    }
    {
        const int sub = tid & 7;
        #pragma unroll
        for (int p = 0; p < 8; p++) {
            const int r = p * 32 + (tid >> 3);
            const float4* src = reinterpret_cast<const float4*>(W + (size_t)r * E_DIM) + sub;
            char* dstrow = smem + BS_OFF + r * (APAD * 2);
            #pragma unroll
            for (int j = 0; j < 8; j++) {
                float4 v = src[j * 8];
                *reinterpret_cast<uint2*>(dstrow + (sub + j * 8) * 8) =
                    make_uint2(packbf(v.x, v.y), packbf(v.z, v.w));
            }
        }
    }
    __syncthreads();

    const int m0 = wid * 16;
    float c[32][4];
    #pragma unroll
    for (int j = 0; j < 32; j++) { c[j][0] = c[j][1] = c[j][2] = c[j][3] = 0.f; }

    const uint32_t a_addr = sb + AS_OFF + (m0 + (lane & 15)) * (APAD * 2) + (lane >> 4) * 16;
    const uint32_t b_addr = sb + BS_OFF + (lane & 7) * (APAD * 2) + ((lane >> 3) & 1) * 16;

    for (int k = 0; k < 16; k++) {
        uint32_t a[4];
        ldsm_x4(a, a_addr + k * 32);
        #pragma unroll
        for (int j = 0; j < 32; j++) {
            uint32_t b[2];
            ldsm_x2(b, b_addr + j * 8 * (APAD * 2) + k * 32);
            mma_bf16(c[j], a, b);
        }
    }

    float* outp = g_xw + (size_t)t * (B_DIM * U_DIM);
    const int r0 = m0 + (lane >> 2), c0 = (lane & 3) * 2;
    #pragma unroll
    for (int j = 0; j < 32; j++) {
        const int col = j * 8 + c0;
        *reinterpret_cast<float2*>(outp + r0 * U_DIM + col)       = make_float2(c[j][0], c[j][1]);
        *reinterpret_cast<float2*>(outp + (r0 + 8) * U_DIM + col) = make_float2(c[j][2], c[j][3]);
    }
}

// ---------------- Kernel 2: deep-ILP batch-split recurrence ----------------
// 16 CTAs x 8 batch rows, 512 threads. Warp wid owns u-tile [16*wid, +16).
// U in SMEM (528B rows), A-fragments ldsm'd per k-tile (xw_kernel's pattern) —
// frees 64 regs, funding EIGHT accumulator chains of depth 2 (32 chains/SMSP,
// matching xw_kernel's ILP that sustains ~11.7 cyc/HMMA). B = h (bf16 smem,
// double-buffered). Epilogue: tree-merge, +xw, tanh, movmatrix, 2 STS.
// xw staged per-step into double-buffered smem via cp.async.

static constexpr int HSTRIDE = 528;                  // bytes per b-row (264 bf16)
static constexpr int HBUF    = 8 * HSTRIDE;          // 4224 per buffer
// dynamic smem offsets
static constexpr int R_US   = 0;                     // U: 256 rows x 528B = 135168
static constexpr int R_HB   = 135168;                // h: 2 x 4224
static constexpr int R_XWS  = R_HB + 2 * HBUF;       // xw stage: 2 x 8192
static constexpr int R_HFIN = R_XWS + 16384;         // 8x256 fp32 = 8192
static constexpr int R_HID  = R_HFIN + 8192;         // 8x32 fp32 = 1024
static constexpr int RNN_SMEM = R_HID + 1024;        // 169216 bytes

__global__ void __launch_bounds__(512, 1)
rnn_kernel(const float* __restrict__ Um, const float* __restrict__ W1,
           const float* __restrict__ b1, const float* __restrict__ W2,
           const float* __restrict__ b2, float* __restrict__ out) {
    extern __shared__ char smem[];
    const int tid = threadIdx.x, wid = tid >> 5, lane = tid & 31;
    const int b0 = blockIdx.x * 8;
    const int u0 = wid * 16;
    const int r = lane >> 2, q = lane & 3;
    const uint32_t sb = smem_u32(smem);

    // ---- stage U into smem (256 rows, 528B stride, bf16) ----
    {
        const int sub = tid & 7;
        #pragma unroll
        for (int p = 0; p < 4; p++) {
            const int row = p * 64 + (tid >> 3);
            const float4* src = reinterpret_cast<const float4*>(Um + (size_t)row * U_DIM) + sub;
            char* dst = smem + R_US + row * HSTRIDE;
            #pragma unroll
            for (int j = 0; j < 8; j++) {
                float4 v = src[j * 8];
                *reinterpret_cast<uint2*>(dst + (sub + j * 8) * 8) =
                    make_uint2(packbf(v.x, v.y), packbf(v.z, v.w));
            }
        }
    }
    // zero both h buffers (h0 = 0)
    for (int i = tid; i < (2 * HBUF) / 4; i += 512)
        reinterpret_cast<uint32_t*>(smem + R_HB)[i] = 0;

    // prologue: stage xw(0) into buffer 0 (512 threads x 16B = 8KB)
    const uint32_t xw_smem = sb + R_XWS;
    cpasync16(xw_smem + tid * 16,
              reinterpret_cast<const char*>(g_xw + (size_t)b0 * U_DIM) + tid * 16);
    asm volatile("cp.async.commit_group;" ::: "memory");
    asm volatile("cp.async.wait_group 0;" ::: "memory");
    __syncthreads();

    const uint32_t hb = sb + R_HB;
    const uint32_t rd0 = hb + (lane & 7) * HSTRIDE + (lane >> 3) * 16;     // B (h)
    const uint32_t ab  = sb + R_US + (u0 + (lane & 15)) * HSTRIDE + (lane >> 4) * 16; // A (U)
    const uint32_t so0 = r * HSTRIDE + (u0 + 2 * q) * 2;                   // trans-store
    const int xo = (2 * q) * 256 + u0 + r;
    float* hfin = reinterpret_cast<float*>(smem + R_HFIN);
    float* hid  = reinterpret_cast<float*>(smem + R_HID);

    for (int t = 0; t < T_DIM; t++) {
        if (t + 1 < T_DIM) {                             // stage xw(t+1)
            cpasync16(xw_smem + ((t + 1) & 1) * 8192 + tid * 16,
                      reinterpret_cast<const char*>(
                          g_xw + (size_t)(t + 1) * (B_DIM * U_DIM) + (size_t)b0 * U_DIM) + tid * 16);
        }
        asm volatile("cp.async.commit_group;" ::: "memory");

        const uint32_t rb = rd0 + (t & 1) * HBUF;
        float acc[8][4];
        #pragma unroll
        for (int i = 0; i < 8; i++)
            #pragma unroll
            for (int j = 0; j < 4; j++) acc[i][j] = 0.f;

        #pragma unroll
        for (int kb = 0; kb < 8; kb++) {                 // k32 blocks
            uint32_t bq[4], a0[4], a1[4];
            ldsm_x4(bq, rb + kb * 64);                   // h: two n8k16 frags
            ldsm_x4(a0, ab + (2 * kb) * 32);             // U: m16k16 frag (k-tile 2kb)
            ldsm_x4(a1, ab + (2 * kb + 1) * 32);         // U: k-tile 2kb+1
            mma_bf16(acc[(2 * kb) & 7],     a0, bq);     // 8 chains, depth 2
            mma_bf16(acc[(2 * kb + 1) & 7], a1, bq + 2);
        }
        // tree-merge the 8 chains
        float m0, m1, m2, m3;
        {
            float s0[4], s1[4], s2[4], s3[4];
            #pragma unroll
            for (int j = 0; j < 4; j++) {
                s0[j] = acc[0][j] + acc[1][j];
                s1[j] = acc[2][j] + acc[3][j];
                s2[j] = acc[4][j] + acc[5][j];
                s3[j] = acc[6][j] + acc[7][j];
            }
            m0 = (s0[0] + s1[0]) + (s2[0] + s3[0]);
            m1 = (s0[1] + s1[1]) + (s2[1] + s3[1]);
            m2 = (s0[2] + s1[2]) + (s2[2] + s3[2]);
            m3 = (s0[3] + s1[3]) + (s2[3] + s3[3]);
        }

        const float* xs = reinterpret_cast<const float*>(smem + R_XWS) + (t & 1) * (8 * 256) + xo;
        float h0 = m0 + xs[0];
        float h1 = m1 + xs[256];
        float h2 = m2 + xs[8];
        float h3 = m3 + xs[264];
        asm("tanh.approx.f32 %0, %1;" : "=f"(h0) : "f"(h0));
        asm("tanh.approx.f32 %0, %1;" : "=f"(h1) : "f"(h1));
        asm("tanh.approx.f32 %0, %1;" : "=f"(h2) : "f"(h2));
        asm("tanh.approx.f32 %0, %1;" : "=f"(h3) : "f"(h3));

        if (t == T_DIM - 1) {                            // fp32 h for the head
            hfin[(2 * q) * 256 + u0 + r]         = h0;
            hfin[(2 * q + 1) * 256 + u0 + r]     = h1;
            hfin[(2 * q) * 256 + u0 + r + 8]     = h2;
            hfin[(2 * q + 1) * 256 + u0 + r + 8] = h3;
        }

        uint32_t g0 = packbf(h0, h1), g1 = packbf(h2, h3);
        uint32_t t0, t1;                                 // transpose (u,b) -> (b,u)
        asm("movmatrix.sync.aligned.m8n8.trans.b16 %0, %1;" : "=r"(t0) : "r"(g0));
        asm("movmatrix.sync.aligned.m8n8.trans.b16 %0, %1;" : "=r"(t1) : "r"(g1));

        const uint32_t wa = hb + (uint32_t)(((t & 1) ^ 1) * HBUF) + so0;
        asm volatile("st.shared.b32 [%0], %1;" :: "r"(wa),      "r"(t0));
        asm volatile("st.shared.b32 [%0], %1;" :: "r"(wa + 16), "r"(t1));

        asm volatile("cp.async.wait_group 0;" ::: "memory");  // xw(t+1) landed
        __syncthreads();                                      // h(t+1) + xw visible
    }

    // ---- head: hidden = relu(hfin @ W1 + b1); logits -> softmax ----
    if (tid < 256) {                       // 8 rows x 32 units
        const int rr = tid >> 5, j = tid & 31;
        float a = b1[j];
        #pragma unroll 8
        for (int k = 0; k < 256; k++) a = fmaf(hfin[rr * 256 + k], W1[k * 32 + j], a);
        hid[rr * 32 + j] = fmaxf(a, 0.0f);
    }
    __syncthreads();
    if (tid < 8) {
        float l0 = b2[0], l1 = b2[1];
        #pragma unroll
        for (int j = 0; j < 32; j++) {
            float x = hid[tid * 32 + j];
            l0 += x * W2[j * 2 + 0];
            l1 += x * W2[j * 2 + 1];
        }
        float mx = fmaxf(l0, l1);
        float e0 = __expf(l0 - mx), e1 = __expf(l1 - mx);
        float inv = 1.0f / (e0 + e1);
        out[(b0 + tid) * 2 + 0] = e0 * inv;
        out[(b0 + tid) * 2 + 1] = e1 * inv;
    }
}

// ---------------- launch ----------------
extern "C" void kernel_launch(void* const* d_in, const int* in_sizes, int n_in,
                              void* d_out, int out_size) {
    const int*   sentence = (const int*)  d_in[0];
    const float* emb      = (const float*)d_in[1];
    const float* W        = (const float*)d_in[2];
    const float* Um       = (const float*)d_in[3];
    const float* W1       = (const float*)d_in[4];
    const float* b1       = (const float*)d_in[5];
    const float* W2       = (const float*)d_in[6];
    const float* b2       = (const float*)d_in[7];
    float* out = (float*)d_out;

    cudaFuncSetAttribute(xw_kernel,  cudaFuncAttributeMaxDynamicSharedMemorySize, XW_SMEM);
    cudaFuncSetAttribute(rnn_kernel, cudaFuncAttributeMaxDynamicSharedMemorySize, RNN_SMEM);

    xw_kernel<<<T_DIM, 256, XW_SMEM>>>(sentence, emb, W);
    rnn_kernel<<<B_DIM / 8, 512, RNN_SMEM>>>(Um, W1, b1, W2, b2, out);
}